// round 6
// baseline (speedup 1.0000x reference)
#include <cuda_runtime.h>
#include <cuda_fp16.h>
#include <math.h>
#include <stdint.h>

#define N_ROWS  131072
#define S_DIM   64
#define H_DIM   128
#define K_CODES 512
#define A_DIM   8
#define TM      128
#define NTHREADS 256
#define MARGIN  1e-3f

typedef uint32_t u32;

// ===================== warp-level tensor ops (base PTX) =====================
#define LDSM4(r, addr)                                                        \
    asm volatile("ldmatrix.sync.aligned.m8n8.x4.shared.b16 {%0,%1,%2,%3}, [%4];" \
                 : "=r"((r)[0]), "=r"((r)[1]), "=r"((r)[2]), "=r"((r)[3])     \
                 : "r"(addr))

__device__ __forceinline__ void mma16816(float* c, const u32* a, u32 b0, u32 b1) {
    asm volatile("mma.sync.aligned.m16n8k16.row.col.f32.f16.f16.f32 "
                 "{%0,%1,%2,%3}, {%4,%5,%6,%7}, {%8,%9}, {%0,%1,%2,%3};"
                 : "+f"(c[0]), "+f"(c[1]), "+f"(c[2]), "+f"(c[3])
                 : "r"(a[0]), "r"(a[1]), "r"(a[2]), "r"(a[3]), "r"(b0), "r"(b1));
}

__device__ __forceinline__ u32 smem_u32(const void* p) {
    u32 a; asm("{ .reg .u64 t; cvta.to.shared.u64 t, %1; cvt.u32.u64 %0, t; }"
               : "=r"(a) : "l"(p)); return a;
}
__device__ __forceinline__ u32 pkh(float a, float b) {
    __half2 t; t.x = __float2half_rn(a); t.y = __float2half_rn(b);
    return *reinterpret_cast<u32*>(&t);
}
__device__ __forceinline__ void cpa16(u32 dst, const void* src) {
    asm volatile("cp.async.cg.shared.global [%0], [%1], 16;"
                 :: "r"(dst), "l"(src) : "memory");
}
#define CP_COMMIT() asm volatile("cp.async.commit_group;" ::: "memory")
#define CP_WAIT(n)  asm volatile("cp.async.wait_group %0;" :: "n"(n) : "memory")

// ===================== device globals =====================
__device__ float g_ee[K_CODES];
__device__ float g_probs[K_CODES * A_DIM];
__device__ float g_value[K_CODES];

// fp16 hi/lo weight & codebook images:
//  W1T: [n=128][k=64] pitch 72 halves, hi then lo
//  WhT: [n=128][k=128] pitch 136 halves, hi then lo
//  E:   4 tiles x { [c=128][d=128] pitch 136 hi, lo }
#define IMG_W1 0
#define IMG_WH 18432
#define IMG_E  53248
#define IMG_TOTAL 192512
__device__ __half g_img[IMG_TOTAL];

// ===================== kernel 1: merged prelim (tables + images) ============
__global__ void prep_all(const float* __restrict__ emb,
                         const float* __restrict__ Wa, const float* __restrict__ ba,
                         const float* __restrict__ Wv, const float* __restrict__ bv,
                         const float* __restrict__ W1, const float* __restrict__ Wh)
{
    if (blockIdx.x < 64) {
        // ---- per-code tables: warp per code ----
        int code = blockIdx.x * 8 + (threadIdx.x >> 5);
        int lane = threadIdx.x & 31;
        const float* e = emb + code * H_DIM;
        double ee = 0.0;
        float logit[A_DIM];
#pragma unroll
        for (int a = 0; a < A_DIM; a++) logit[a] = 0.0f;
        float val = 0.0f;
#pragma unroll
        for (int j = 0; j < 4; j++) {
            int d = lane + 32 * j;
            float ej = e[d];
            ee += (double)ej * (double)ej;
#pragma unroll
            for (int a = 0; a < A_DIM; a++) logit[a] = fmaf(ej, Wa[d * A_DIM + a], logit[a]);
            val = fmaf(ej, Wv[d], val);
        }
#pragma unroll
        for (int off = 16; off; off >>= 1) {
            ee  += __shfl_xor_sync(0xFFFFFFFFu, ee,  off);
            val += __shfl_xor_sync(0xFFFFFFFFu, val, off);
#pragma unroll
            for (int a = 0; a < A_DIM; a++)
                logit[a] += __shfl_xor_sync(0xFFFFFFFFu, logit[a], off);
        }
        if (lane == 0) {
#pragma unroll
            for (int a = 0; a < A_DIM; a++) logit[a] += ba[a];
            g_ee[code] = (float)ee;
            g_value[code] = val + bv[0];
            float m = logit[0];
#pragma unroll
            for (int a = 1; a < A_DIM; a++) m = fmaxf(m, logit[a]);
            float p[A_DIM], s = 0.0f;
#pragma unroll
            for (int a = 0; a < A_DIM; a++) { p[a] = expf(logit[a] - m); s += p[a]; }
#pragma unroll
            for (int a = 0; a < A_DIM; a++) g_probs[code * A_DIM + a] = p[a] / s;
        }
        return;
    }
    // ---- hi/lo images ----
    int idx = (blockIdx.x - 64) * 256 + threadIdx.x;
    if (idx < 8192) {                       // W1T
        int n = idx >> 6, s = idx & 63;
        float v = W1[s * H_DIM + n];
        __half h = __float2half_rn(v);
        __half l = __float2half_rn(v - __half2float(h));
        int o = n * 72 + s;
        g_img[IMG_W1 + o] = h;
        g_img[IMG_W1 + 9216 + o] = l;
    } else if (idx < 24576) {               // WhT
        int j = idx - 8192;
        int n = j >> 7, k = j & 127;
        float v = Wh[k * H_DIM + n];
        __half h = __float2half_rn(v);
        __half l = __float2half_rn(v - __half2float(h));
        int o = n * 136 + k;
        g_img[IMG_WH + o] = h;
        g_img[IMG_WH + 17408 + o] = l;
    } else if (idx < 90112) {               // E tiles
        int j = idx - 24576;
        int g = j >> 7, d = j & 127;
        int t = g >> 7, c = g & 127;
        float v = emb[g * H_DIM + d];
        __half h = __float2half_rn(v);
        __half l = __float2half_rn(v - __half2float(h));
        int o = c * 136 + d;
        g_img[IMG_E + t * 34816 + o] = h;
        g_img[IMG_E + t * 34816 + 17408 + o] = l;
    }
}

// ===================== kernel 2: fused main =====================
// SMEM byte map:
#define OFF_B1   0        // float[128]
#define OFF_BH   512
#define OFF_VV   1024     // float[128][2]
#define OFF_EE   2048     // float[512]
#define OFF_CD   4096     // float[128][4]
#define OFF_CI   6144     // int[128][4]
#define REG_A    8192     // input hi|lo(+18432) p144; W1 hi(+36864)|lo(+55296); later x2 hi|lo(+34816) p272
#define REG_C    81920    // x1 hi|lo(+34816) p272; later E tiles 0,2
#define REG_D    151552   // Wh hi|lo(+34816) p272; later E tiles 1,3
#define SMEM_BYTES 221184

// 3-pass split GEMM, warp tile 32 rows x 64 cols (2 m-groups, 4 bt blocks)
// acc layout: acc[m*8 + 2*bt + {0,1}][4]
__device__ __forceinline__ void run_gemm32(int ksteps, u32 aH, u32 aL, u32 bH, u32 bL,
                                           int pitchA, int pitchB,
                                           int lane, int wrow, int cbase, float (*acc)[4])
{
    const u32 aoff0 = (u32)(wrow + (lane & 15)) * pitchA + (u32)(lane >> 4) * 16;
    const u32 aoff1 = aoff0 + 16u * pitchA;
    const u32 boff = (u32)(cbase + (lane & 7) + ((lane >> 4) << 3)) * pitchB
                   + (u32)((lane >> 3) & 1) * 16;
    for (int ks = 0; ks < ksteps; ks++) {
        u32 ah0[4], al0[4], ah1[4], al1[4];
        LDSM4(ah0, aH + aoff0 + ks * 32);
        LDSM4(al0, aL + aoff0 + ks * 32);
        LDSM4(ah1, aH + aoff1 + ks * 32);
        LDSM4(al1, aL + aoff1 + ks * 32);
#pragma unroll
        for (int bt = 0; bt < 4; bt++) {
            u32 bh[4], bl[4];
            LDSM4(bh, bH + boff + (u32)bt * 16 * pitchB + ks * 32);
            mma16816(acc[2 * bt],         ah0, bh[0], bh[1]);
            mma16816(acc[2 * bt + 1],     ah0, bh[2], bh[3]);
            mma16816(acc[8 + 2 * bt],     ah1, bh[0], bh[1]);
            mma16816(acc[8 + 2 * bt + 1], ah1, bh[2], bh[3]);
            mma16816(acc[2 * bt],         al0, bh[0], bh[1]);
            mma16816(acc[2 * bt + 1],     al0, bh[2], bh[3]);
            mma16816(acc[8 + 2 * bt],     al1, bh[0], bh[1]);
            mma16816(acc[8 + 2 * bt + 1], al1, bh[2], bh[3]);
            LDSM4(bl, bL + boff + (u32)bt * 16 * pitchB + ks * 32);
            mma16816(acc[2 * bt],         ah0, bl[0], bl[1]);
            mma16816(acc[2 * bt + 1],     ah0, bl[2], bl[3]);
            mma16816(acc[8 + 2 * bt],     ah1, bl[0], bl[1]);
            mma16816(acc[8 + 2 * bt + 1], ah1, bl[2], bl[3]);
        }
    }
}

__global__ __launch_bounds__(NTHREADS, 1)
void fused_kernel(const float* __restrict__ in,
                  const float* __restrict__ b1, const float* __restrict__ bh,
                  const float* __restrict__ emb,
                  float* __restrict__ out)
{
    extern __shared__ __align__(16) unsigned char smem[];
    const u32 sb = smem_u32(smem);
    char* sc = (char*)smem;

    const int tid   = threadIdx.x;
    const int wid   = tid >> 5;
    const int lane  = tid & 31;
    const int g     = lane >> 2;
    const int q     = lane & 3;
    const int wrow  = (wid & 3) * 32;      // 32-row strip
    const int chalf = wid >> 2;            // column half
    const int cbase = chalf * 64;
    const int rowBase = blockIdx.x * TM;

    float* sB1 = (float*)(sc + OFF_B1);
    float* sBH = (float*)(sc + OFF_BH);
    float* sVV = (float*)(sc + OFF_VV);
    float* sEE = (float*)(sc + OFF_EE);
    float* sCD = (float*)(sc + OFF_CD);
    int*   sCI = (int*)  (sc + OFF_CI);

    const char* gimg = (const char*)g_img;

    // ---------------- Stage 0: prefetch W1, Wh; split input ----------------
    for (int i = tid; i < 2304; i += NTHREADS)                    // W1 images
        cpa16(sb + REG_A + 36864 + i * 16, gimg + IMG_W1 * 2 + i * 16);
    CP_COMMIT();
    for (int i = tid; i < 4352; i += NTHREADS)                    // Wh images
        cpa16(sb + REG_D + i * 16, gimg + IMG_WH * 2 + i * 16);
    CP_COMMIT();

    for (int p = tid; p < 128 * 32; p += NTHREADS) {              // input split
        int row = p >> 5, pc = p & 31;
        float2 v = *(const float2*)(in + (size_t)(rowBase + row) * S_DIM + 2 * pc);
        __half h0 = __float2half_rn(v.x);
        __half h1 = __float2half_rn(v.y);
        u32 o = (u32)row * 144 + (u32)pc * 4;
        *(u32*)(sc + REG_A + o)         = pkh(__half2float(h0), __half2float(h1));
        *(u32*)(sc + REG_A + 18432 + o) = pkh(v.x - __half2float(h0), v.y - __half2float(h1));
    }
    if (tid < 128) { sB1[tid] = b1[tid]; sBH[tid] = bh[tid]; }
    for (int i = tid; i < 512; i += NTHREADS) sEE[i] = g_ee[i];
    CP_WAIT(1);
    __syncthreads();

    float acc[16][4];

    // ---------------- Stage 1: x1 = relu(in @ W1 + b1) ----------------
#pragma unroll
    for (int t = 0; t < 16; t++)
#pragma unroll
        for (int j = 0; j < 4; j++) acc[t][j] = 0.0f;
    run_gemm32(4, sb + REG_A, sb + REG_A + 18432,
               sb + REG_A + 36864, sb + REG_A + 55296, 144, 144, lane, wrow, cbase, acc);
#pragma unroll
    for (int m = 0; m < 2; m++) {
        int r1 = wrow + m * 16 + g, r2 = r1 + 8;
#pragma unroll
        for (int t = 0; t < 8; t++) {
            int c = cbase + 8 * t + 2 * q;
            float* a = acc[m * 8 + t];
            float z0 = fmaxf(a[0] + sB1[c],     0.0f);
            float z1 = fmaxf(a[1] + sB1[c + 1], 0.0f);
            float z2 = fmaxf(a[2] + sB1[c],     0.0f);
            float z3 = fmaxf(a[3] + sB1[c + 1], 0.0f);
            __half h0 = __float2half_rn(z0), h1 = __float2half_rn(z1);
            __half h2 = __float2half_rn(z2), h3 = __float2half_rn(z3);
            u32 o1 = (u32)r1 * 272 + (u32)c * 2;
            u32 o2 = (u32)r2 * 272 + (u32)c * 2;
            *(u32*)(sc + REG_C + o1)         = pkh(__half2float(h0), __half2float(h1));
            *(u32*)(sc + REG_C + o2)         = pkh(__half2float(h2), __half2float(h3));
            *(u32*)(sc + REG_C + 34816 + o1) = pkh(z0 - __half2float(h0), z1 - __half2float(h1));
            *(u32*)(sc + REG_C + 34816 + o2) = pkh(z2 - __half2float(h2), z3 - __half2float(h3));
        }
    }
    CP_WAIT(0);
    __syncthreads();

    // ---------------- Stage 2: x2 = relu(x1 @ Wh + bh) ----------------
#pragma unroll
    for (int t = 0; t < 16; t++)
#pragma unroll
        for (int j = 0; j < 4; j++) acc[t][j] = 0.0f;
    run_gemm32(8, sb + REG_C, sb + REG_C + 34816,
               sb + REG_D, sb + REG_D + 34816, 272, 272, lane, wrow, cbase, acc);
    __syncthreads();   // MMA reads of REG_C/REG_D complete

    // prefetch E tiles 0, 1
    for (int i = tid; i < 4352; i += NTHREADS)
        cpa16(sb + REG_C + i * 16, gimg + IMG_E * 2 + i * 16);
    CP_COMMIT();
    for (int i = tid; i < 4352; i += NTHREADS)
        cpa16(sb + REG_D + i * 16, gimg + IMG_E * 2 + 69632 + i * 16);
    CP_COMMIT();

    // stage 2 epilogue (overlaps fills)
    {
        float vp[2][2] = {{0.0f, 0.0f}, {0.0f, 0.0f}};
#pragma unroll
        for (int m = 0; m < 2; m++) {
            int r1 = wrow + m * 16 + g, r2 = r1 + 8;
#pragma unroll
            for (int t = 0; t < 8; t++) {
                int c = cbase + 8 * t + 2 * q;
                float* a = acc[m * 8 + t];
                float z0 = fmaxf(a[0] + sBH[c],     0.0f);
                float z1 = fmaxf(a[1] + sBH[c + 1], 0.0f);
                float z2 = fmaxf(a[2] + sBH[c],     0.0f);
                float z3 = fmaxf(a[3] + sBH[c + 1], 0.0f);
                __half h0 = __float2half_rn(z0), h1 = __float2half_rn(z1);
                __half h2 = __float2half_rn(z2), h3 = __float2half_rn(z3);
                float fl0 = z0 - __half2float(h0), fl1 = z1 - __half2float(h1);
                float fl2 = z2 - __half2float(h2), fl3 = z3 - __half2float(h3);
                float x0 = __half2float(h0) + __half2float(__float2half_rn(fl0));
                float x1 = __half2float(h1) + __half2float(__float2half_rn(fl1));
                float x2 = __half2float(h2) + __half2float(__float2half_rn(fl2));
                float x3 = __half2float(h3) + __half2float(__float2half_rn(fl3));
                vp[m][0] = fmaf(x0, x0, vp[m][0]); vp[m][0] = fmaf(x1, x1, vp[m][0]);
                vp[m][1] = fmaf(x2, x2, vp[m][1]); vp[m][1] = fmaf(x3, x3, vp[m][1]);
                u32 o1 = (u32)r1 * 272 + (u32)c * 2;
                u32 o2 = (u32)r2 * 272 + (u32)c * 2;
                *(u32*)(sc + REG_A + o1)         = pkh(__half2float(h0), __half2float(h1));
                *(u32*)(sc + REG_A + o2)         = pkh(__half2float(h2), __half2float(h3));
                *(u32*)(sc + REG_A + 34816 + o1) = pkh(fl0, fl1);
                *(u32*)(sc + REG_A + 34816 + o2) = pkh(fl2, fl3);
            }
        }
#pragma unroll
        for (int m = 0; m < 2; m++)
#pragma unroll
            for (int h = 0; h < 2; h++) {
                float v = vp[m][h];
                v += __shfl_xor_sync(0xFFFFFFFFu, v, 1);
                v += __shfl_xor_sync(0xFFFFFFFFu, v, 2);
                if (q == 0) sVV[(wrow + m * 16 + g + 8 * h) * 2 + chalf] = v;
            }
    }
    __syncthreads();

    // ---------------- Score: 4 tiles, double-buffered ----------------
    float vvr[2][2];
#pragma unroll
    for (int m = 0; m < 2; m++)
#pragma unroll
        for (int h = 0; h < 2; h++) {
            int r = wrow + m * 16 + g + 8 * h;
            vvr[m][h] = sVV[r * 2] + sVV[r * 2 + 1];
        }
    float b1d[4], b2d[4];
    int b1i[4], b2i[4];
#pragma unroll
    for (int s = 0; s < 4; s++) {
        b1d[s] = __int_as_float(0x7f800000); b2d[s] = b1d[s];
        b1i[s] = 0; b2i[s] = 0;
    }

    for (int tile = 0; tile < 4; tile++) {
        if (tile == 3) { CP_WAIT(0); } else { CP_WAIT(1); }
        __syncthreads();
        u32 buf = (tile & 1) ? (sb + REG_D) : (sb + REG_C);

#pragma unroll
        for (int t = 0; t < 16; t++)
#pragma unroll
            for (int j = 0; j < 4; j++) acc[t][j] = 0.0f;
        run_gemm32(8, sb + REG_A, sb + REG_A + 34816,
                   buf, buf + 34816, 272, 272, lane, wrow, cbase, acc);

        int codeBase = tile * 128 + cbase;
#pragma unroll
        for (int m = 0; m < 2; m++)
#pragma unroll
            for (int t = 0; t < 8; t++) {
                int c = codeBase + 8 * t + 2 * q;
                float* a = acc[m * 8 + t];
#pragma unroll
                for (int jj = 0; jj < 2; jj++) {
                    int code = c + jj;
                    float ee = sEE[code];
                    float d1 = fmaf(-2.0f, a[jj],     vvr[m][0]) + ee;
                    float d2 = fmaf(-2.0f, a[2 + jj], vvr[m][1]) + ee;
                    int s1 = m * 2, s2 = m * 2 + 1;
                    if (d1 < b1d[s1]) { b2d[s1] = b1d[s1]; b2i[s1] = b1i[s1]; b1d[s1] = d1; b1i[s1] = code; }
                    else if (d1 < b2d[s1]) { b2d[s1] = d1; b2i[s1] = code; }
                    if (d2 < b1d[s2]) { b2d[s2] = b1d[s2]; b2i[s2] = b1i[s2]; b1d[s2] = d2; b1i[s2] = code; }
                    else if (d2 < b2d[s2]) { b2d[s2] = d2; b2i[s2] = code; }
                }
            }

        if (tile < 2) {
            __syncthreads();   // buffer reads complete before refill
            u32 dst = (tile & 1) ? (sb + REG_D) : (sb + REG_C);
            const char* src = gimg + IMG_E * 2 + (tile + 2) * 69632;
            for (int i = tid; i < 4352; i += NTHREADS)
                cpa16(dst + i * 16, src + i * 16);
            CP_COMMIT();
        }
    }

    // ---------------- merge top-2 across q lanes ----------------
#pragma unroll
    for (int s = 0; s < 4; s++) {
#pragma unroll
        for (int mk = 1; mk <= 2; mk <<= 1) {
            float o1 = __shfl_xor_sync(0xFFFFFFFFu, b1d[s], mk);
            int  oi1 = __shfl_xor_sync(0xFFFFFFFFu, b1i[s], mk);
            float o2 = __shfl_xor_sync(0xFFFFFFFFu, b2d[s], mk);
            int  oi2 = __shfl_xor_sync(0xFFFFFFFFu, b2i[s], mk);
            if (o1 < b1d[s]) { b2d[s] = b1d[s]; b2i[s] = b1i[s]; b1d[s] = o1; b1i[s] = oi1; }
            else if (o1 < b2d[s]) { b2d[s] = o1; b2i[s] = oi1; }
            if (o2 < b2d[s]) { b2d[s] = o2; b2i[s] = oi2; }
        }
    }
    if (q == 0) {
#pragma unroll
        for (int s = 0; s < 4; s++) {
            int r = wrow + (s >> 1) * 16 + g + 8 * (s & 1);
            sCD[r * 4 + chalf * 2]     = b1d[s];  sCI[r * 4 + chalf * 2]     = b1i[s];
            sCD[r * 4 + chalf * 2 + 1] = b2d[s];  sCI[r * 4 + chalf * 2 + 1] = b2i[s];
        }
    }
    __syncthreads();

    // ---------------- candidates + exact fp32 re-check + output ----------------
    if (tid < TM) {
        int row = tid;
        float cd[4]; int ci[4];
#pragma unroll
        for (int j = 0; j < 4; j++) { cd[j] = sCD[row * 4 + j]; ci[j] = sCI[row * 4 + j]; }
        float mn = fminf(fminf(cd[0], cd[1]), fminf(cd[2], cd[3]));
        int cnt = 0; int cidx[4];
#pragma unroll
        for (int j = 0; j < 4; j++)
            if (cd[j] <= mn + MARGIN) cidx[cnt++] = ci[j];

        int bestI;
        if (cnt == 1) {
            bestI = cidx[0];
        } else {
            float dots[4] = {0.0f, 0.0f, 0.0f, 0.0f};
            float vx = 0.0f;
            for (int i = 0; i < 64; i++) {
                int w = (row + i) & 63;
                u32 hw = *(const u32*)(sc + REG_A + (u32)row * 272 + (u32)w * 4);
                u32 lw = *(const u32*)(sc + REG_A + 34816 + (u32)row * 272 + (u32)w * 4);
                __half2 hh = *reinterpret_cast<__half2*>(&hw);
                __half2 ll = *reinterpret_cast<__half2*>(&lw);
                float x0 = __half2float(hh.x) + __half2float(ll.x);
                float x1 = __half2float(hh.y) + __half2float(ll.y);
                vx = fmaf(x0, x0, vx);
                vx = fmaf(x1, x1, vx);
                for (int j = 0; j < cnt; j++) {
                    const float* ep = emb + (size_t)cidx[j] * H_DIM + 2 * w;
                    dots[j] = fmaf(x0, __ldg(ep),     dots[j]);
                    dots[j] = fmaf(x1, __ldg(ep + 1), dots[j]);
                }
            }
            float bestD = __int_as_float(0x7f800000);
            bestI = 0x7fffffff;
            for (int j = 0; j < cnt; j++) {
                float dd = __fadd_rn(__fsub_rn(vx, __fmul_rn(2.0f, dots[j])), sEE[cidx[j]]);
                if (dd < bestD || (dd == bestD && cidx[j] < bestI)) { bestD = dd; bestI = cidx[j]; }
            }
        }

        int gr = rowBase + row;
        float4 p0 = *(const float4*)(g_probs + bestI * A_DIM);
        float4 p1 = *(const float4*)(g_probs + bestI * A_DIM + 4);
        float4* po = (float4*)out;
        po[gr * 2 + 0] = p0;
        po[gr * 2 + 1] = p1;
        out[(size_t)N_ROWS * A_DIM + gr] = g_value[bestI];
    }
}

// ===================== launch =====================
extern "C" void kernel_launch(void* const* d_in, const int* in_sizes, int n_in,
                              void* d_out, int out_size)
{
    const float* inputs = (const float*)d_in[0];
    const float* W1  = (const float*)d_in[1];
    const float* b1  = (const float*)d_in[2];
    const float* Wh  = (const float*)d_in[3];
    const float* bh  = (const float*)d_in[4];
    const float* emb = (const float*)d_in[5];
    const float* Wa  = (const float*)d_in[6];
    const float* ba  = (const float*)d_in[7];
    const float* Wv  = (const float*)d_in[8];
    const float* bv  = (const float*)d_in[9];

    cudaFuncSetAttribute(fused_kernel,
                         cudaFuncAttributeMaxDynamicSharedMemorySize, SMEM_BYTES);

    prep_all<<<416, 256>>>(emb, Wa, ba, Wv, bv, W1, Wh);
    fused_kernel<<<N_ROWS / TM, NTHREADS, SMEM_BYTES>>>(
        inputs, b1, bh, emb, (float*)d_out);
}

// round 7
// speedup vs baseline: 1.0974x; 1.0974x over previous
#include <cuda_runtime.h>
#include <cuda_fp16.h>
#include <math.h>
#include <stdint.h>

#define N_ROWS  131072
#define S_DIM   64
#define H_DIM   128
#define K_CODES 512
#define A_DIM   8
#define TM      128
#define NTHREADS 512
#define MARGIN  1e-3f

typedef uint32_t u32;

// ===================== warp-level tensor ops (base PTX) =====================
#define LDSM4(r, addr)                                                        \
    asm volatile("ldmatrix.sync.aligned.m8n8.x4.shared.b16 {%0,%1,%2,%3}, [%4];" \
                 : "=r"((r)[0]), "=r"((r)[1]), "=r"((r)[2]), "=r"((r)[3])     \
                 : "r"(addr))

__device__ __forceinline__ void mma16816(float* c, const u32* a, u32 b0, u32 b1) {
    asm volatile("mma.sync.aligned.m16n8k16.row.col.f32.f16.f16.f32 "
                 "{%0,%1,%2,%3}, {%4,%5,%6,%7}, {%8,%9}, {%0,%1,%2,%3};"
                 : "+f"(c[0]), "+f"(c[1]), "+f"(c[2]), "+f"(c[3])
                 : "r"(a[0]), "r"(a[1]), "r"(a[2]), "r"(a[3]), "r"(b0), "r"(b1));
}

__device__ __forceinline__ u32 smem_u32(const void* p) {
    u32 a; asm("{ .reg .u64 t; cvta.to.shared.u64 t, %1; cvt.u32.u64 %0, t; }"
               : "=r"(a) : "l"(p)); return a;
}
__device__ __forceinline__ u32 pkh(float a, float b) {
    __half2 t; t.x = __float2half_rn(a); t.y = __float2half_rn(b);
    return *reinterpret_cast<u32*>(&t);
}
__device__ __forceinline__ void cpa16(u32 dst, const void* src) {
    asm volatile("cp.async.cg.shared.global [%0], [%1], 16;"
                 :: "r"(dst), "l"(src) : "memory");
}
#define CP_COMMIT() asm volatile("cp.async.commit_group;" ::: "memory")
#define CP_WAIT(n)  asm volatile("cp.async.wait_group %0;" :: "n"(n) : "memory")

// ===================== device globals =====================
__device__ float g_ee[K_CODES];
__device__ float g_probs[K_CODES * A_DIM];
__device__ float g_value[K_CODES];

// fp16 hi/lo weight & codebook images:
//  W1T: [n=128][k=64] pitch 72 halves, hi then lo
//  WhT: [n=128][k=128] pitch 136 halves, hi then lo
//  E:   4 tiles x { [c=128][d=128] pitch 136 hi, lo }
#define IMG_W1 0
#define IMG_WH 18432
#define IMG_E  53248
__device__ __half g_img[192512];

// ===================== kernel 1: merged prelim (tables + images) ============
__global__ void prep_all(const float* __restrict__ emb,
                         const float* __restrict__ Wa, const float* __restrict__ ba,
                         const float* __restrict__ Wv, const float* __restrict__ bv,
                         const float* __restrict__ W1, const float* __restrict__ Wh)
{
    if (blockIdx.x < 64) {
        int code = blockIdx.x * 8 + (threadIdx.x >> 5);
        int lane = threadIdx.x & 31;
        const float* e = emb + code * H_DIM;
        double ee = 0.0;
        float logit[A_DIM];
#pragma unroll
        for (int a = 0; a < A_DIM; a++) logit[a] = 0.0f;
        float val = 0.0f;
#pragma unroll
        for (int j = 0; j < 4; j++) {
            int d = lane + 32 * j;
            float ej = e[d];
            ee += (double)ej * (double)ej;
#pragma unroll
            for (int a = 0; a < A_DIM; a++) logit[a] = fmaf(ej, Wa[d * A_DIM + a], logit[a]);
            val = fmaf(ej, Wv[d], val);
        }
#pragma unroll
        for (int off = 16; off; off >>= 1) {
            ee  += __shfl_xor_sync(0xFFFFFFFFu, ee,  off);
            val += __shfl_xor_sync(0xFFFFFFFFu, val, off);
#pragma unroll
            for (int a = 0; a < A_DIM; a++)
                logit[a] += __shfl_xor_sync(0xFFFFFFFFu, logit[a], off);
        }
        if (lane == 0) {
#pragma unroll
            for (int a = 0; a < A_DIM; a++) logit[a] += ba[a];
            g_ee[code] = (float)ee;
            g_value[code] = val + bv[0];
            float m = logit[0];
#pragma unroll
            for (int a = 1; a < A_DIM; a++) m = fmaxf(m, logit[a]);
            float p[A_DIM], s = 0.0f;
#pragma unroll
            for (int a = 0; a < A_DIM; a++) { p[a] = expf(logit[a] - m); s += p[a]; }
#pragma unroll
            for (int a = 0; a < A_DIM; a++) g_probs[code * A_DIM + a] = p[a] / s;
        }
        return;
    }
    int idx = (blockIdx.x - 64) * 256 + threadIdx.x;
    if (idx < 8192) {                       // W1T
        int n = idx >> 6, s = idx & 63;
        float v = W1[s * H_DIM + n];
        __half h = __float2half_rn(v);
        __half l = __float2half_rn(v - __half2float(h));
        int o = n * 72 + s;
        g_img[IMG_W1 + o] = h;
        g_img[IMG_W1 + 9216 + o] = l;
    } else if (idx < 24576) {               // WhT
        int j = idx - 8192;
        int n = j >> 7, k = j & 127;
        float v = Wh[k * H_DIM + n];
        __half h = __float2half_rn(v);
        __half l = __float2half_rn(v - __half2float(h));
        int o = n * 136 + k;
        g_img[IMG_WH + o] = h;
        g_img[IMG_WH + 17408 + o] = l;
    } else if (idx < 90112) {               // E tiles
        int j = idx - 24576;
        int g = j >> 7, d = j & 127;
        int t = g >> 7, c = g & 127;
        float v = emb[g * H_DIM + d];
        __half h = __float2half_rn(v);
        __half l = __float2half_rn(v - __half2float(h));
        int o = c * 136 + d;
        g_img[IMG_E + t * 34816 + o] = h;
        g_img[IMG_E + t * 34816 + 17408 + o] = l;
    }
}

// ===================== kernel 2: fused main =====================
// SMEM byte map:
#define OFF_B1   0        // float[128]
#define OFF_BH   512
#define OFF_VV   1024     // float[128][4]
#define OFF_EE   3072     // float[512]
#define OFF_CD   5120     // float[128][8]
#define OFF_CI   9216     // int[128][8]
#define REG_A    14336    // input hi|lo(+18432) p144; W1 hi(+36864)|lo(+55296); later x2 hi|lo(+34816) p272
#define REG_C    88064    // x1 hi|lo(+34816) p272; later E tiles 0,2
#define REG_D    157696   // Wh hi|lo(+34816) p272; later E tiles 1,3
#define SMEM_BYTES 227328

// 3-pass split GEMM, warp tile 32 rows x 32 cols; pass-major MMA ordering.
// acc[m*4 + bt*2 + n][4]
template<int KS>
__device__ __forceinline__ void run_gemm(u32 aH, u32 aL, u32 bH, u32 bL,
                                         int pitchA, int pitchB,
                                         int lane, int wrow, int cbase, float (*acc)[4])
{
    const u32 aoff0 = (u32)(wrow + (lane & 15)) * pitchA + (u32)(lane >> 4) * 16;
    const u32 aoff1 = aoff0 + 16u * pitchA;
    const u32 boff = (u32)(cbase + (lane & 7) + ((lane >> 4) << 3)) * pitchB
                   + (u32)((lane >> 3) & 1) * 16;
#pragma unroll
    for (int ks = 0; ks < KS; ks++) {
        u32 ah0[4], al0[4], ah1[4], al1[4];
        u32 bh0[4], bh1[4], bl0[4], bl1[4];
        LDSM4(ah0, aH + aoff0 + ks * 32);
        LDSM4(ah1, aH + aoff1 + ks * 32);
        LDSM4(bh0, bH + boff + ks * 32);
        LDSM4(bh1, bH + boff + 16u * pitchB + ks * 32);
        LDSM4(al0, aL + aoff0 + ks * 32);
        LDSM4(al1, aL + aoff1 + ks * 32);
        LDSM4(bl0, bL + boff + ks * 32);
        LDSM4(bl1, bL + boff + 16u * pitchB + ks * 32);
        // pass 1: hi*hi
        mma16816(acc[0], ah0, bh0[0], bh0[1]);
        mma16816(acc[1], ah0, bh0[2], bh0[3]);
        mma16816(acc[2], ah0, bh1[0], bh1[1]);
        mma16816(acc[3], ah0, bh1[2], bh1[3]);
        mma16816(acc[4], ah1, bh0[0], bh0[1]);
        mma16816(acc[5], ah1, bh0[2], bh0[3]);
        mma16816(acc[6], ah1, bh1[0], bh1[1]);
        mma16816(acc[7], ah1, bh1[2], bh1[3]);
        // pass 2: lo*hi
        mma16816(acc[0], al0, bh0[0], bh0[1]);
        mma16816(acc[1], al0, bh0[2], bh0[3]);
        mma16816(acc[2], al0, bh1[0], bh1[1]);
        mma16816(acc[3], al0, bh1[2], bh1[3]);
        mma16816(acc[4], al1, bh0[0], bh0[1]);
        mma16816(acc[5], al1, bh0[2], bh0[3]);
        mma16816(acc[6], al1, bh1[0], bh1[1]);
        mma16816(acc[7], al1, bh1[2], bh1[3]);
        // pass 3: hi*lo
        mma16816(acc[0], ah0, bl0[0], bl0[1]);
        mma16816(acc[1], ah0, bl0[2], bl0[3]);
        mma16816(acc[2], ah0, bl1[0], bl1[1]);
        mma16816(acc[3], ah0, bl1[2], bl1[3]);
        mma16816(acc[4], ah1, bl0[0], bl0[1]);
        mma16816(acc[5], ah1, bl0[2], bl0[3]);
        mma16816(acc[6], ah1, bl1[0], bl1[1]);
        mma16816(acc[7], ah1, bl1[2], bl1[3]);
    }
}

__global__ __launch_bounds__(NTHREADS, 1)
void fused_kernel(const float* __restrict__ in,
                  const float* __restrict__ b1, const float* __restrict__ bh,
                  const float* __restrict__ emb,
                  float* __restrict__ out)
{
    extern __shared__ __align__(16) unsigned char smem[];
    const u32 sb = smem_u32(smem);
    char* sc = (char*)smem;

    const int tid    = threadIdx.x;
    const int wid    = tid >> 5;
    const int lane   = tid & 31;
    const int g      = lane >> 2;
    const int q      = lane & 3;
    const int wrow   = (wid & 3) * 32;     // 32-row strip
    const int cquart = wid >> 2;           // 32-col quarter
    const int cbase  = cquart * 32;
    const int rowBase = blockIdx.x * TM;

    float* sB1 = (float*)(sc + OFF_B1);
    float* sBH = (float*)(sc + OFF_BH);
    float* sVV = (float*)(sc + OFF_VV);
    float* sEE = (float*)(sc + OFF_EE);
    float* sCD = (float*)(sc + OFF_CD);
    int*   sCI = (int*)  (sc + OFF_CI);

    const char* gimg = (const char*)g_img;

    // ---------------- Stage 0: prefetch W1, Wh; split input ----------------
    for (int i = tid; i < 2304; i += NTHREADS)
        cpa16(sb + REG_A + 36864 + i * 16, gimg + IMG_W1 * 2 + i * 16);
    CP_COMMIT();
    for (int i = tid; i < 4352; i += NTHREADS)
        cpa16(sb + REG_D + i * 16, gimg + IMG_WH * 2 + i * 16);
    CP_COMMIT();

    for (int p = tid; p < 128 * 32; p += NTHREADS) {
        int row = p >> 5, pc = p & 31;
        float2 v = *(const float2*)(in + (size_t)(rowBase + row) * S_DIM + 2 * pc);
        __half h0 = __float2half_rn(v.x);
        __half h1 = __float2half_rn(v.y);
        u32 o = (u32)row * 144 + (u32)pc * 4;
        *(u32*)(sc + REG_A + o)         = pkh(__half2float(h0), __half2float(h1));
        *(u32*)(sc + REG_A + 18432 + o) = pkh(v.x - __half2float(h0), v.y - __half2float(h1));
    }
    if (tid < 128) { sB1[tid] = b1[tid]; sBH[tid] = bh[tid]; }
    if (tid < 512) sEE[tid] = g_ee[tid];
    CP_WAIT(1);
    __syncthreads();

    float acc[8][4];

    // ---------------- Stage 1: x1 = relu(in @ W1 + b1) ----------------
#pragma unroll
    for (int t = 0; t < 8; t++)
#pragma unroll
        for (int j = 0; j < 4; j++) acc[t][j] = 0.0f;
    run_gemm<4>(sb + REG_A, sb + REG_A + 18432,
                sb + REG_A + 36864, sb + REG_A + 55296, 144, 144, lane, wrow, cbase, acc);
#pragma unroll
    for (int m = 0; m < 2; m++) {
        int r1 = wrow + m * 16 + g, r2 = r1 + 8;
#pragma unroll
        for (int bt = 0; bt < 2; bt++)
#pragma unroll
            for (int n = 0; n < 2; n++) {
                int c = cbase + bt * 16 + n * 8 + 2 * q;
                float* a = acc[m * 4 + bt * 2 + n];
                float z0 = fmaxf(a[0] + sB1[c],     0.0f);
                float z1 = fmaxf(a[1] + sB1[c + 1], 0.0f);
                float z2 = fmaxf(a[2] + sB1[c],     0.0f);
                float z3 = fmaxf(a[3] + sB1[c + 1], 0.0f);
                __half h0 = __float2half_rn(z0), h1 = __float2half_rn(z1);
                __half h2 = __float2half_rn(z2), h3 = __float2half_rn(z3);
                u32 o1 = (u32)r1 * 272 + (u32)c * 2;
                u32 o2 = (u32)r2 * 272 + (u32)c * 2;
                *(u32*)(sc + REG_C + o1)         = pkh(__half2float(h0), __half2float(h1));
                *(u32*)(sc + REG_C + o2)         = pkh(__half2float(h2), __half2float(h3));
                *(u32*)(sc + REG_C + 34816 + o1) = pkh(z0 - __half2float(h0), z1 - __half2float(h1));
                *(u32*)(sc + REG_C + 34816 + o2) = pkh(z2 - __half2float(h2), z3 - __half2float(h3));
            }
    }
    CP_WAIT(0);
    __syncthreads();

    // ---------------- Stage 2: x2 = relu(x1 @ Wh + bh) ----------------
#pragma unroll
    for (int t = 0; t < 8; t++)
#pragma unroll
        for (int j = 0; j < 4; j++) acc[t][j] = 0.0f;
    run_gemm<8>(sb + REG_C, sb + REG_C + 34816,
                sb + REG_D, sb + REG_D + 34816, 272, 272, lane, wrow, cbase, acc);
    __syncthreads();   // MMA reads of REG_C/REG_D complete

    // prefetch E tiles 0, 1
    for (int i = tid; i < 4352; i += NTHREADS)
        cpa16(sb + REG_C + i * 16, gimg + IMG_E * 2 + i * 16);
    CP_COMMIT();
    for (int i = tid; i < 4352; i += NTHREADS)
        cpa16(sb + REG_D + i * 16, gimg + IMG_E * 2 + 69632 + i * 16);
    CP_COMMIT();

    // stage 2 epilogue (overlaps fills)
    {
        float vp[2][2] = {{0.0f, 0.0f}, {0.0f, 0.0f}};
#pragma unroll
        for (int m = 0; m < 2; m++) {
            int r1 = wrow + m * 16 + g, r2 = r1 + 8;
#pragma unroll
            for (int bt = 0; bt < 2; bt++)
#pragma unroll
                for (int n = 0; n < 2; n++) {
                    int c = cbase + bt * 16 + n * 8 + 2 * q;
                    float* a = acc[m * 4 + bt * 2 + n];
                    float z0 = fmaxf(a[0] + sBH[c],     0.0f);
                    float z1 = fmaxf(a[1] + sBH[c + 1], 0.0f);
                    float z2 = fmaxf(a[2] + sBH[c],     0.0f);
                    float z3 = fmaxf(a[3] + sBH[c + 1], 0.0f);
                    __half h0 = __float2half_rn(z0), h1 = __float2half_rn(z1);
                    __half h2 = __float2half_rn(z2), h3 = __float2half_rn(z3);
                    float fl0 = z0 - __half2float(h0), fl1 = z1 - __half2float(h1);
                    float fl2 = z2 - __half2float(h2), fl3 = z3 - __half2float(h3);
                    float x0 = __half2float(h0) + __half2float(__float2half_rn(fl0));
                    float x1 = __half2float(h1) + __half2float(__float2half_rn(fl1));
                    float x2 = __half2float(h2) + __half2float(__float2half_rn(fl2));
                    float x3 = __half2float(h3) + __half2float(__float2half_rn(fl3));
                    vp[m][0] = fmaf(x0, x0, vp[m][0]); vp[m][0] = fmaf(x1, x1, vp[m][0]);
                    vp[m][1] = fmaf(x2, x2, vp[m][1]); vp[m][1] = fmaf(x3, x3, vp[m][1]);
                    u32 o1 = (u32)r1 * 272 + (u32)c * 2;
                    u32 o2 = (u32)r2 * 272 + (u32)c * 2;
                    *(u32*)(sc + REG_A + o1)         = pkh(__half2float(h0), __half2float(h1));
                    *(u32*)(sc + REG_A + o2)         = pkh(__half2float(h2), __half2float(h3));
                    *(u32*)(sc + REG_A + 34816 + o1) = pkh(fl0, fl1);
                    *(u32*)(sc + REG_A + 34816 + o2) = pkh(fl2, fl3);
                }
        }
#pragma unroll
        for (int m = 0; m < 2; m++)
#pragma unroll
            for (int h = 0; h < 2; h++) {
                float v = vp[m][h];
                v += __shfl_xor_sync(0xFFFFFFFFu, v, 1);
                v += __shfl_xor_sync(0xFFFFFFFFu, v, 2);
                if (q == 0) sVV[(wrow + m * 16 + g + 8 * h) * 4 + cquart] = v;
            }
    }
    __syncthreads();

    // ---------------- Score: 4 tiles, double-buffered ----------------
    float vvr[2][2];
#pragma unroll
    for (int m = 0; m < 2; m++)
#pragma unroll
        for (int h = 0; h < 2; h++) {
            int r = wrow + m * 16 + g + 8 * h;
            vvr[m][h] = (sVV[r * 4] + sVV[r * 4 + 1]) + (sVV[r * 4 + 2] + sVV[r * 4 + 3]);
        }
    float b1d[4], b2d[4];
    int b1i[4], b2i[4];
#pragma unroll
    for (int s = 0; s < 4; s++) {
        b1d[s] = __int_as_float(0x7f800000); b2d[s] = b1d[s];
        b1i[s] = 0; b2i[s] = 0;
    }

    for (int tile = 0; tile < 4; tile++) {
        if (tile == 3) { CP_WAIT(0); } else { CP_WAIT(1); }
        __syncthreads();
        u32 buf = (tile & 1) ? (sb + REG_D) : (sb + REG_C);

#pragma unroll
        for (int t = 0; t < 8; t++)
#pragma unroll
            for (int j = 0; j < 4; j++) acc[t][j] = 0.0f;
        run_gemm<8>(sb + REG_A, sb + REG_A + 34816,
                    buf, buf + 34816, 272, 272, lane, wrow, cbase, acc);

        int codeBase = tile * 128 + cbase;
#pragma unroll
        for (int m = 0; m < 2; m++)
#pragma unroll
            for (int bt = 0; bt < 2; bt++)
#pragma unroll
                for (int n = 0; n < 2; n++) {
                    int c = codeBase + bt * 16 + n * 8 + 2 * q;
                    float* a = acc[m * 4 + bt * 2 + n];
#pragma unroll
                    for (int jj = 0; jj < 2; jj++) {
                        int code = c + jj;
                        float ee = sEE[code];
                        float d1 = fmaf(-2.0f, a[jj],     vvr[m][0]) + ee;
                        float d2 = fmaf(-2.0f, a[2 + jj], vvr[m][1]) + ee;
                        int s1 = m * 2, s2 = m * 2 + 1;
                        if (d1 < b1d[s1]) { b2d[s1] = b1d[s1]; b2i[s1] = b1i[s1]; b1d[s1] = d1; b1i[s1] = code; }
                        else if (d1 < b2d[s1]) { b2d[s1] = d1; b2i[s1] = code; }
                        if (d2 < b1d[s2]) { b2d[s2] = b1d[s2]; b2i[s2] = b1i[s2]; b1d[s2] = d2; b1i[s2] = code; }
                        else if (d2 < b2d[s2]) { b2d[s2] = d2; b2i[s2] = code; }
                    }
                }

        if (tile < 2) {
            __syncthreads();   // buffer reads complete before refill
            u32 dst = (tile & 1) ? (sb + REG_D) : (sb + REG_C);
            const char* src = gimg + IMG_E * 2 + (tile + 2) * 69632;
            for (int i = tid; i < 4352; i += NTHREADS)
                cpa16(dst + i * 16, src + i * 16);
            CP_COMMIT();
        }
    }

    // ---------------- merge top-2 across q lanes ----------------
#pragma unroll
    for (int s = 0; s < 4; s++) {
#pragma unroll
        for (int mk = 1; mk <= 2; mk <<= 1) {
            float o1 = __shfl_xor_sync(0xFFFFFFFFu, b1d[s], mk);
            int  oi1 = __shfl_xor_sync(0xFFFFFFFFu, b1i[s], mk);
            float o2 = __shfl_xor_sync(0xFFFFFFFFu, b2d[s], mk);
            int  oi2 = __shfl_xor_sync(0xFFFFFFFFu, b2i[s], mk);
            if (o1 < b1d[s]) { b2d[s] = b1d[s]; b2i[s] = b1i[s]; b1d[s] = o1; b1i[s] = oi1; }
            else if (o1 < b2d[s]) { b2d[s] = o1; b2i[s] = oi1; }
            if (o2 < b2d[s]) { b2d[s] = o2; b2i[s] = oi2; }
        }
    }
    if (q == 0) {
#pragma unroll
        for (int s = 0; s < 4; s++) {
            int r = wrow + (s >> 1) * 16 + g + 8 * (s & 1);
            sCD[r * 8 + cquart * 2]     = b1d[s];  sCI[r * 8 + cquart * 2]     = b1i[s];
            sCD[r * 8 + cquart * 2 + 1] = b2d[s];  sCI[r * 8 + cquart * 2 + 1] = b2i[s];
        }
    }
    __syncthreads();

    // ---------------- candidates + exact fp32 re-check + output ----------------
    if (tid < TM) {
        int row = tid;
        float cd[8]; int ci[8];
#pragma unroll
        for (int j = 0; j < 8; j++) { cd[j] = sCD[row * 8 + j]; ci[j] = sCI[row * 8 + j]; }
        float mn = cd[0];
#pragma unroll
        for (int j = 1; j < 8; j++) mn = fminf(mn, cd[j]);
        int cnt = 0; int cidx[8];
#pragma unroll
        for (int j = 0; j < 8; j++)
            if (cd[j] <= mn + MARGIN) cidx[cnt++] = ci[j];

        int bestI;
        if (cnt == 1) {
            bestI = cidx[0];
        } else {
            float dots[8];
#pragma unroll
            for (int j = 0; j < 8; j++) dots[j] = 0.0f;
            float vx = 0.0f;
            for (int i = 0; i < 64; i++) {
                int w = (row + i) & 63;
                u32 hw = *(const u32*)(sc + REG_A + (u32)row * 272 + (u32)w * 4);
                u32 lw = *(const u32*)(sc + REG_A + 34816 + (u32)row * 272 + (u32)w * 4);
                __half2 hh = *reinterpret_cast<__half2*>(&hw);
                __half2 ll = *reinterpret_cast<__half2*>(&lw);
                float x0 = __half2float(hh.x) + __half2float(ll.x);
                float x1 = __half2float(hh.y) + __half2float(ll.y);
                vx = fmaf(x0, x0, vx);
                vx = fmaf(x1, x1, vx);
                for (int j = 0; j < cnt; j++) {
                    const float* ep = emb + (size_t)cidx[j] * H_DIM + 2 * w;
                    dots[j] = fmaf(x0, __ldg(ep),     dots[j]);
                    dots[j] = fmaf(x1, __ldg(ep + 1), dots[j]);
                }
            }
            float bestD = __int_as_float(0x7f800000);
            bestI = 0x7fffffff;
            for (int j = 0; j < cnt; j++) {
                float dd = __fadd_rn(__fsub_rn(vx, __fmul_rn(2.0f, dots[j])), sEE[cidx[j]]);
                if (dd < bestD || (dd == bestD && cidx[j] < bestI)) { bestD = dd; bestI = cidx[j]; }
            }
        }

        int gr = rowBase + row;
        float4 p0 = *(const float4*)(g_probs + bestI * A_DIM);
        float4 p1 = *(const float4*)(g_probs + bestI * A_DIM + 4);
        float4* po = (float4*)out;
        po[gr * 2 + 0] = p0;
        po[gr * 2 + 1] = p1;
        out[(size_t)N_ROWS * A_DIM + gr] = g_value[bestI];
    }
}

// ===================== launch =====================
extern "C" void kernel_launch(void* const* d_in, const int* in_sizes, int n_in,
                              void* d_out, int out_size)
{
    const float* inputs = (const float*)d_in[0];
    const float* W1  = (const float*)d_in[1];
    const float* b1  = (const float*)d_in[2];
    const float* Wh  = (const float*)d_in[3];
    const float* bh  = (const float*)d_in[4];
    const float* emb = (const float*)d_in[5];
    const float* Wa  = (const float*)d_in[6];
    const float* ba  = (const float*)d_in[7];
    const float* Wv  = (const float*)d_in[8];
    const float* bv  = (const float*)d_in[9];

    cudaFuncSetAttribute(fused_kernel,
                         cudaFuncAttributeMaxDynamicSharedMemorySize, SMEM_BYTES);

    prep_all<<<416, 256>>>(emb, Wa, ba, Wv, bv, W1, Wh);
    fused_kernel<<<N_ROWS / TM, NTHREADS, SMEM_BYTES>>>(
        inputs, b1, bh, emb, (float*)d_out);
}